// round 2
// baseline (speedup 1.0000x reference)
#include <cuda_runtime.h>
#include <cuda_fp16.h>
#include <stdint.h>

// StackedUnidirLSTMDecoder: B=64, L=4, H=1024, T=128
#define BB    64
#define LL    4
#define HH    1024
#define TT    128
#define GG    4096
#define NCTA  128
#define NTHR  128
#define KT_L  64              // k-tiles (of 16) per 1024-wide half
#define ROWH  2048            // halfs per packed A row (hi+lo interleaved)

// ---------------------------------------------------------------------------
// Device-global scratch (no runtime allocation allowed)
// ---------------------------------------------------------------------------
// W packed in mma B-fragment order, fp16:
// [L][NCTA][kt=128][np=2][lane=32][8 halfs]  (np pairs two n8-tiles)
__device__ __half g_Wp[(size_t)LL * NCTA * 128 * 512];

// Activations packed in mma A-fragment order, hi/lo fp16 split interleaved:
// addr(r,k): ((r*64 + (k>>4))*4 + ((k>>1)&3))*8 + (k&1) + ((k>>3)&1)*2 ; lo at +4
__device__ __half g_Xp[LL][BB * ROWH];        // layer input (layer0 = fed-back y)
__device__ __half g_Hp[2][LL][BB * ROWH];     // recurrent h, parity = t&1
__device__ float  g_c[LL * BB * HH];          // cell state
__device__ unsigned g_bar_cnt;                // returns to 0 after each barrier
__device__ unsigned g_bar_gen;

__device__ __host__ __forceinline__ int packA(int r, int k) {
    return ((r * KT_L + (k >> 4)) * 4 + ((k >> 1) & 3)) * 8
           + (k & 1) + ((k >> 3) & 1) * 2;
}

// ---------------------------------------------------------------------------
// Prologue 1: pack W_ih|W_hh (fp32 [L][4H][H] each) into fragment order fp16
// ---------------------------------------------------------------------------
__global__ void pack_weights(const float* __restrict__ Wih,
                             const float* __restrict__ Whh) {
    int tid = blockIdx.x * blockDim.x + threadIdx.x;
    if (tid >= LL * NCTA * 128 * 32) return;
    int lane = tid & 31;
    int kt   = (tid >> 5) & 127;
    int cta  = (tid >> 12) & 127;
    int l    = tid >> 19;
    int c8 = lane >> 2;           // n within n8 tile
    int kq = (lane & 3) * 2;      // base k of this thread's quad

    #pragma unroll
    for (int np = 0; np < 2; np++) {
        #pragma unroll
        for (int ntl = 0; ntl < 2; ntl++) {
            int nt = np * 2 + ntl;                 // gate index
            int n  = nt * 1024 + cta * 8 + c8;
            __half v[4];
            #pragma unroll
            for (int e = 0; e < 4; e++) {
                int k = kt * 16 + kq + (e & 1) + 8 * (e >> 1);
                float w = (k < HH) ? Wih[((size_t)l * GG + n) * HH + k]
                                   : Whh[((size_t)l * GG + n) * HH + (k - HH)];
                v[e] = __float2half(w);
            }
            size_t off = ((((size_t)(l * NCTA + cta) * 128 + kt) * 2 + np) * 32
                          + lane) * 8 + ntl * 4;
            *(uint2*)&g_Wp[off] = *(uint2*)v;
        }
    }
}

// ---------------------------------------------------------------------------
// Prologue 2: init state (x -> g_Xp[0], h0 -> g_Hp[0], c0 -> g_c), hi/lo split
// ---------------------------------------------------------------------------
__global__ void init_state(const float* __restrict__ x,
                           const float* __restrict__ h0,
                           const float* __restrict__ c0) {
    int i = blockIdx.x * blockDim.x + threadIdx.x;
    if (i >= LL * BB * HH) return;
    int k = i & (HH - 1);
    int r = (i >> 10) & (BB - 1);
    int l = i >> 16;
    g_c[i] = c0[i];

    int pa = packA(r, k);
    float hv = h0[i];
    __half hhi = __float2half(hv);
    __half hlo = __float2half((hv - __half2float(hhi)) * 2048.0f);
    g_Hp[0][l][pa] = hhi;  g_Hp[0][l][pa + 4] = hlo;

    if (l == 0) {
        float xv = x[r * HH + k];
        __half xhi = __float2half(xv);
        __half xlo = __float2half((xv - __half2float(xhi)) * 2048.0f);
        g_Xp[0][pa] = xhi;  g_Xp[0][pa + 4] = xlo;
    }
}

// ---------------------------------------------------------------------------
// Grid barrier: release/acquire via fences, sense-reversal generation counter
// ---------------------------------------------------------------------------
__device__ __forceinline__ void grid_sync() {
    __threadfence();           // release: all this thread's stores visible
    __syncthreads();
    if (threadIdx.x == 0) {
        unsigned gen = atomicAdd(&g_bar_gen, 0u);
        if (atomicAdd(&g_bar_cnt, 1u) == NCTA - 1) {
            atomicExch(&g_bar_cnt, 0u);
            __threadfence();
            atomicAdd(&g_bar_gen, 1u);
        } else {
            while (atomicAdd(&g_bar_gen, 0u) == gen) __nanosleep(32);
        }
        __threadfence();       // acquire
    }
    __syncthreads();
}

__device__ __forceinline__ void mma16816(float* d,
                                         unsigned a0, unsigned a1, unsigned a2, unsigned a3,
                                         unsigned b0, unsigned b1) {
    asm volatile(
        "mma.sync.aligned.m16n8k16.row.col.f32.f16.f16.f32 "
        "{%0,%1,%2,%3},{%4,%5,%6,%7},{%8,%9},{%0,%1,%2,%3};\n"
        : "+f"(d[0]), "+f"(d[1]), "+f"(d[2]), "+f"(d[3])
        : "r"(a0), "r"(a1), "r"(a2), "r"(a3), "r"(b0), "r"(b1));
}

__device__ __forceinline__ float sigm(float v) { return 1.0f / (1.0f + __expf(-v)); }

// ---------------------------------------------------------------------------
// Persistent LSTM: 512 lock-stepped cell-steps, one grid sync each.
// CTA c owns gate columns {g*1024 + j : g in 0..3, j in [8c, 8c+8)} so every
// thread holds i,f,g,o for its (b,j) in registers -> register-local cell update.
// ---------------------------------------------------------------------------
__global__ void __launch_bounds__(NTHR, 1)
lstm_persistent(const float* __restrict__ b_ih,
                const float* __restrict__ b_hh,
                float* __restrict__ out) {
    const int cta  = blockIdx.x;
    const int warp = threadIdx.x >> 5;
    const int lane = threadIdx.x & 31;
    const int m0   = warp * 16;
    const int qrow = lane >> 2;
    const int tq   = lane & 3;
    const int qcol = tq * 2;

    // biases hoisted: [l][gate][u]  (l unrolled below -> stays in registers)
    float bias[LL][4][2];
    #pragma unroll
    for (int l = 0; l < LL; l++)
        #pragma unroll
        for (int g = 0; g < 4; g++)
            #pragma unroll
            for (int u = 0; u < 2; u++) {
                int j = cta * 8 + qcol + u;
                bias[l][g][u] = b_ih[l * GG + g * 1024 + j]
                              + b_hh[l * GG + g * 1024 + j];
            }

    for (int t = 0; t < TT; t++) {
        const int p = t & 1;
        #pragma unroll
        for (int l = 0; l < LL; l++) {
            const __half* __restrict__ Wl = g_Wp + (size_t)(l * NCTA + cta) * 65536;

            float acc[4][4], accl[4][4];
            #pragma unroll
            for (int a = 0; a < 4; a++)
                #pragma unroll
                for (int b = 0; b < 4; b++) { acc[a][b] = 0.0f; accl[a][b] = 0.0f; }

            #pragma unroll
            for (int half = 0; half < 2; half++) {
                const __half* __restrict__ Ab = half ? g_Hp[p][l] : g_Xp[l];
                const uint4* a0p = (const uint4*)(Ab + (size_t)(((m0 + qrow)     * KT_L) * 4 + tq) * 8);
                const uint4* a1p = (const uint4*)(Ab + (size_t)(((m0 + qrow + 8) * KT_L) * 4 + tq) * 8);
                const uint4* wp  = (const uint4*)(Wl + (size_t)half * KT_L * 512);

                #pragma unroll 2
                for (int kk = 0; kk < KT_L; kk++) {
                    uint4 va0 = a0p[kk * 4];              // a0_hi,a2_hi,a0_lo,a2_lo
                    uint4 va1 = a1p[kk * 4];              // a1_hi,a3_hi,a1_lo,a3_lo
                    uint4 w01 = wp[kk * 64 + lane];       // B-frags nt0, nt1
                    uint4 w23 = wp[kk * 64 + 32 + lane];  // B-frags nt2, nt3
                    mma16816(acc[0],  va0.x, va1.x, va0.y, va1.y, w01.x, w01.y);
                    mma16816(acc[1],  va0.x, va1.x, va0.y, va1.y, w01.z, w01.w);
                    mma16816(acc[2],  va0.x, va1.x, va0.y, va1.y, w23.x, w23.y);
                    mma16816(acc[3],  va0.x, va1.x, va0.y, va1.y, w23.z, w23.w);
                    mma16816(accl[0], va0.z, va1.z, va0.w, va1.w, w01.x, w01.y);
                    mma16816(accl[1], va0.z, va1.z, va0.w, va1.w, w01.z, w01.w);
                    mma16816(accl[2], va0.z, va1.z, va0.w, va1.w, w23.x, w23.y);
                    mma16816(accl[3], va0.z, va1.z, va0.w, va1.w, w23.z, w23.w);
                }
            }

            // ---- cell update: i,f,g,o for same (r,j) live in this thread ----
            __half* __restrict__ hdst = g_Hp[p ^ 1][l];
            __half* __restrict__ xdst = (l < LL - 1) ? g_Xp[l + 1] : g_Xp[0]; // y feedback!
            float*  __restrict__ cl   = g_c + l * BB * HH;

            #pragma unroll
            for (int hh2 = 0; hh2 < 2; hh2++) {
                int r = m0 + qrow + hh2 * 8;
                #pragma unroll
                for (int u = 0; u < 2; u++) {
                    int j  = cta * 8 + qcol + u;
                    int ci = hh2 * 2 + u;
                    const float s = 1.0f / 2048.0f;
                    float gi = acc[0][ci] + accl[0][ci] * s + bias[l][0][u];
                    float gf = acc[1][ci] + accl[1][ci] * s + bias[l][1][u];
                    float gg = acc[2][ci] + accl[2][ci] * s + bias[l][2][u];
                    float go = acc[3][ci] + accl[3][ci] * s + bias[l][3][u];
                    float ig = sigm(gi), fg = sigm(gf), og = sigm(go);
                    float gt = tanhf(gg);
                    float cn = fg * cl[r * HH + j] + ig * gt;
                    cl[r * HH + j] = cn;
                    float hn = og * tanhf(cn);
                    __half vhi = __float2half(hn);
                    __half vlo = __float2half((hn - __half2float(vhi)) * 2048.0f);
                    int pa = packA(r, j);
                    hdst[pa] = vhi;  hdst[pa + 4] = vlo;   // recurrent input (l, t+1)
                    xdst[pa] = vhi;  xdst[pa + 4] = vlo;   // next layer / y-feedback
                    if (l == LL - 1) out[((size_t)r * TT + t) * HH + j] = hn;
                }
            }
            grid_sync();
        }
    }
}

// ---------------------------------------------------------------------------
// kernel_launch: pack -> init -> persistent run (all graph-capturable)
// inputs: x, h0, c0, W_ih, W_hh, b_ih, b_hh, seq_len
// ---------------------------------------------------------------------------
extern "C" void kernel_launch(void* const* d_in, const int* in_sizes, int n_in,
                              void* d_out, int out_size) {
    const float* x   = (const float*)d_in[0];
    const float* h0  = (const float*)d_in[1];
    const float* c0  = (const float*)d_in[2];
    const float* Wih = (const float*)d_in[3];
    const float* Whh = (const float*)d_in[4];
    const float* bih = (const float*)d_in[5];
    const float* bhh = (const float*)d_in[6];
    float* out = (float*)d_out;

    pack_weights<<<(LL * NCTA * 128 * 32) / 256, 256>>>(Wih, Whh);
    init_state<<<(LL * BB * HH + 255) / 256, 256>>>(x, h0, c0);
    lstm_persistent<<<NCTA, NTHR>>>(bih, bhh, out);
}

// round 3
// speedup vs baseline: 1.2194x; 1.2194x over previous
#include <cuda_runtime.h>
#include <cuda_fp16.h>
#include <stdint.h>

// StackedUnidirLSTMDecoder: B=64, L=4, H=1024, T=128
#define BB    64
#define LL    4
#define HH    1024
#define TT    128
#define GG    4096
#define NCTA  128
#define NTHR  256             // 8 warps: 0-3 = hi stream, 4-7 = lo stream
#define KT_L  64              // k-tiles (of 16) per 1024-wide half
#define ROWH  2048            // halfs per packed A row (hi+lo interleaved)

// ---------------------------------------------------------------------------
// Device-global scratch (no runtime allocation allowed)
// ---------------------------------------------------------------------------
// W packed in mma B-fragment order, fp16:
// [L][NCTA][kt=128][np=2][lane=32][8 halfs]
__device__ __half g_Wp[(size_t)LL * NCTA * 128 * 512];

// Activations packed in mma A-fragment order, hi/lo fp16 split interleaved:
// group(r,k) = (r*64 + (k>>4))*4 + ((k>>1)&3); within group of 8 halfs:
//   hi at (k&1) + ((k>>3)&1)*2, lo at +4
__device__ __half g_Xp[LL][BB * ROWH];        // layer input (layer0 = fed-back y)
__device__ __half g_Hp[2][LL][BB * ROWH];     // recurrent h, parity = t&1
__device__ unsigned g_bar_cnt;
__device__ unsigned g_bar_gen;

__device__ __host__ __forceinline__ int packA(int r, int k) {
    return ((r * KT_L + (k >> 4)) * 4 + ((k >> 1) & 3)) * 8
           + (k & 1) + ((k >> 3) & 1) * 2;
}

// ---------------------------------------------------------------------------
// Prologue 1: pack W_ih|W_hh (fp32 [L][4H][H] each) into fragment order fp16
// ---------------------------------------------------------------------------
__global__ void pack_weights(const float* __restrict__ Wih,
                             const float* __restrict__ Whh) {
    int tid = blockIdx.x * blockDim.x + threadIdx.x;
    if (tid >= LL * NCTA * 128 * 32) return;
    int lane = tid & 31;
    int kt   = (tid >> 5) & 127;
    int cta  = (tid >> 12) & 127;
    int l    = tid >> 19;
    int c8 = lane >> 2;
    int kq = (lane & 3) * 2;

    #pragma unroll
    for (int np = 0; np < 2; np++) {
        #pragma unroll
        for (int ntl = 0; ntl < 2; ntl++) {
            int nt = np * 2 + ntl;
            int n  = nt * 1024 + cta * 8 + c8;
            __half v[4];
            #pragma unroll
            for (int e = 0; e < 4; e++) {
                int k = kt * 16 + kq + (e & 1) + 8 * (e >> 1);
                float w = (k < HH) ? Wih[((size_t)l * GG + n) * HH + k]
                                   : Whh[((size_t)l * GG + n) * HH + (k - HH)];
                v[e] = __float2half(w);
            }
            size_t off = ((((size_t)(l * NCTA + cta) * 128 + kt) * 2 + np) * 32
                          + lane) * 8 + ntl * 4;
            *(uint2*)&g_Wp[off] = *(uint2*)v;
        }
    }
}

// ---------------------------------------------------------------------------
// Prologue 2: init activations (x -> g_Xp[0], h0 -> g_Hp[0]), hi/lo split
// ---------------------------------------------------------------------------
__global__ void init_state(const float* __restrict__ x,
                           const float* __restrict__ h0) {
    int i = blockIdx.x * blockDim.x + threadIdx.x;
    if (i >= LL * BB * HH) return;
    int k = i & (HH - 1);
    int r = (i >> 10) & (BB - 1);
    int l = i >> 16;

    int pa = packA(r, k);
    float hv = h0[i];
    __half hhi = __float2half(hv);
    __half hlo = __float2half((hv - __half2float(hhi)) * 2048.0f);
    g_Hp[0][l][pa] = hhi;  g_Hp[0][l][pa + 4] = hlo;

    if (l == 0) {
        float xv = x[r * HH + k];
        __half xhi = __float2half(xv);
        __half xlo = __float2half((xv - __half2float(xhi)) * 2048.0f);
        g_Xp[0][pa] = xhi;  g_Xp[0][pa + 4] = xlo;
    }
}

// ---------------------------------------------------------------------------
// Grid barrier (sense-reversal). Grid = 128 CTAs <= 148 SMs, all resident.
// ---------------------------------------------------------------------------
__device__ __forceinline__ void grid_sync() {
    __threadfence();
    __syncthreads();
    if (threadIdx.x == 0) {
        unsigned gen = atomicAdd(&g_bar_gen, 0u);
        if (atomicAdd(&g_bar_cnt, 1u) == NCTA - 1) {
            atomicExch(&g_bar_cnt, 0u);
            __threadfence();
            atomicAdd(&g_bar_gen, 1u);
        } else {
            while (atomicAdd(&g_bar_gen, 0u) == gen) __nanosleep(32);
        }
        __threadfence();
    }
    __syncthreads();
}

__device__ __forceinline__ void mma16816(float* d,
                                         unsigned a0, unsigned a1, unsigned a2, unsigned a3,
                                         unsigned b0, unsigned b1) {
    asm volatile(
        "mma.sync.aligned.m16n8k16.row.col.f32.f16.f16.f32 "
        "{%0,%1,%2,%3},{%4,%5,%6,%7},{%8,%9},{%0,%1,%2,%3};\n"
        : "+f"(d[0]), "+f"(d[1]), "+f"(d[2]), "+f"(d[3])
        : "r"(a0), "r"(a1), "r"(a2), "r"(a3), "r"(b0), "r"(b1));
}

__device__ __forceinline__ float sigm(float v) { return 1.0f / (1.0f + __expf(-v)); }
__device__ __forceinline__ float tanh_fast(float v) {
    return 2.0f / (1.0f + __expf(-2.0f * v)) - 1.0f;
}

// ---------------------------------------------------------------------------
// Persistent LSTM. CTA c owns gate columns {g*1024+j : j in [8c,8c+8)}.
// Warps 0-3: hi stream + cell update (c lives in registers).
// Warps 4-7: lo stream, deposited via SMEM.
// ---------------------------------------------------------------------------
__global__ void __launch_bounds__(NTHR, 1)
lstm_persistent(const float* __restrict__ c0,
                const float* __restrict__ b_ih,
                const float* __restrict__ b_hh,
                float* __restrict__ out) {
    const int cta  = blockIdx.x;
    const int w    = threadIdx.x >> 5;
    const int lane = threadIdx.x & 31;
    const int hilo = w >> 2;             // 0 = hi warps, 1 = lo warps
    const int wm   = w & 3;
    const int m0   = wm * 16;
    const int qrow = lane >> 2;
    const int tq   = lane & 3;
    const int qcol = tq * 2;

    __shared__ float s_lo[4][4][4][32];  // [wm][gate][ci][lane]

    // hi-warp private state: biases and cell state in registers (fixed (r,j))
    float bias[LL][4][2];
    float creg[LL][4];
    if (hilo == 0) {
        #pragma unroll
        for (int l = 0; l < LL; l++) {
            #pragma unroll
            for (int g = 0; g < 4; g++)
                #pragma unroll
                for (int u = 0; u < 2; u++) {
                    int j = cta * 8 + qcol + u;
                    bias[l][g][u] = b_ih[l * GG + g * 1024 + j]
                                  + b_hh[l * GG + g * 1024 + j];
                }
            #pragma unroll
            for (int hh2 = 0; hh2 < 2; hh2++)
                #pragma unroll
                for (int u = 0; u < 2; u++) {
                    int r = m0 + qrow + hh2 * 8;
                    int j = cta * 8 + qcol + u;
                    creg[l][hh2 * 2 + u] = c0[((size_t)l * BB + r) * HH + j];
                }
        }
    }

    for (int t = 0; t < TT; t++) {
        const int p = t & 1;
        #pragma unroll
        for (int l = 0; l < LL; l++) {
            const __half* __restrict__ Wl = g_Wp + (size_t)(l * NCTA + cta) * 65536;

            float acc[4][4];
            #pragma unroll
            for (int a = 0; a < 4; a++)
                #pragma unroll
                for (int b = 0; b < 4; b++) acc[a][b] = 0.0f;

            #pragma unroll
            for (int half = 0; half < 2; half++) {
                const __half* __restrict__ Ab = half ? g_Hp[p][l] : g_Xp[l];
                // byte base of this thread's fragment stream (hi at +0, lo at +8B)
                const char* a0b = (const char*)Ab
                    + (size_t)((m0 + qrow) * KT_L * 4 + tq) * 16 + hilo * 8;
                const char* a1b = a0b + (size_t)8 * KT_L * 4 * 16;
                const uint4* __restrict__ wp =
                    (const uint4*)(Wl + (size_t)half * KT_L * 512);

                #pragma unroll 4
                for (int kk = 0; kk < KT_L; kk++) {
                    uint2 va0 = __ldcg((const uint2*)(a0b + kk * 64)); // (a0,a2)
                    uint2 va1 = __ldcg((const uint2*)(a1b + kk * 64)); // (a1,a3)
                    uint4 w01 = wp[kk * 64 + lane];        // B-frags gate0, gate1
                    uint4 w23 = wp[kk * 64 + 32 + lane];   // B-frags gate2, gate3
                    mma16816(acc[0], va0.x, va1.x, va0.y, va1.y, w01.x, w01.y);
                    mma16816(acc[1], va0.x, va1.x, va0.y, va1.y, w01.z, w01.w);
                    mma16816(acc[2], va0.x, va1.x, va0.y, va1.y, w23.x, w23.y);
                    mma16816(acc[3], va0.x, va1.x, va0.y, va1.y, w23.z, w23.w);
                }
            }

            // lo warps deposit their accumulators
            if (hilo == 1) {
                #pragma unroll
                for (int g = 0; g < 4; g++)
                    #pragma unroll
                    for (int ci = 0; ci < 4; ci++)
                        s_lo[wm][g][ci][lane] = acc[g][ci];
            }
            __syncthreads();

            if (hilo == 0) {
                const float s = 1.0f / 2048.0f;
                #pragma unroll
                for (int g = 0; g < 4; g++)
                    #pragma unroll
                    for (int ci = 0; ci < 4; ci++)
                        acc[g][ci] += s_lo[wm][g][ci][lane] * s;

                __half* __restrict__ hdst = g_Hp[p ^ 1][l];
                __half* __restrict__ xdst = (l < LL - 1) ? g_Xp[l + 1] : g_Xp[0];

                #pragma unroll
                for (int hh2 = 0; hh2 < 2; hh2++) {
                    int r = m0 + qrow + hh2 * 8;
                    #pragma unroll
                    for (int u = 0; u < 2; u++) {
                        int j  = cta * 8 + qcol + u;
                        int ci = hh2 * 2 + u;
                        float gi = acc[0][ci] + bias[l][0][u];
                        float gf = acc[1][ci] + bias[l][1][u];
                        float gg = acc[2][ci] + bias[l][2][u];
                        float go = acc[3][ci] + bias[l][3][u];
                        float ig = sigm(gi), fg = sigm(gf), og = sigm(go);
                        float gt = tanh_fast(gg);
                        float cn = fg * creg[l][ci] + ig * gt;
                        creg[l][ci] = cn;
                        float hn = og * tanh_fast(cn);
                        __half vhi = __float2half(hn);
                        __half vlo = __float2half((hn - __half2float(vhi)) * 2048.0f);
                        int pa = packA(r, j);
                        hdst[pa] = vhi;  hdst[pa + 4] = vlo;   // recurrent (l, t+1)
                        xdst[pa] = vhi;  xdst[pa + 4] = vlo;   // next layer / y-feedback
                        if (l == LL - 1) out[((size_t)r * TT + t) * HH + j] = hn;
                    }
                }
            }
            grid_sync();
        }
    }
}

// ---------------------------------------------------------------------------
// kernel_launch: pack -> init -> persistent run (graph-capturable)
// inputs: x, h0, c0, W_ih, W_hh, b_ih, b_hh, seq_len
// ---------------------------------------------------------------------------
extern "C" void kernel_launch(void* const* d_in, const int* in_sizes, int n_in,
                              void* d_out, int out_size) {
    const float* x   = (const float*)d_in[0];
    const float* h0  = (const float*)d_in[1];
    const float* c0  = (const float*)d_in[2];
    const float* Wih = (const float*)d_in[3];
    const float* Whh = (const float*)d_in[4];
    const float* bih = (const float*)d_in[5];
    const float* bhh = (const float*)d_in[6];
    float* out = (float*)d_out;

    pack_weights<<<(LL * NCTA * 128 * 32) / 256, 256>>>(Wih, Whh);
    init_state<<<(LL * BB * HH + 255) / 256, 256>>>(x, h0);
    lstm_persistent<<<NCTA, NTHR>>>(c0, bih, bhh, out);
}

// round 4
// speedup vs baseline: 4.7641x; 3.9069x over previous
#include <cuda_runtime.h>
#include <cuda_fp16.h>
#include <stdint.h>

// StackedUnidirLSTMDecoder: B=64, L=4, H=1024, T=128
#define BB    64
#define LL    4
#define HH    1024
#define TT    128
#define GG    4096
#define NCTA  128
#define NTHR  512             // 16 warps: (ks 0..3) x (wm 0..3)

// ---------------------------------------------------------------------------
// Device-global scratch
// ---------------------------------------------------------------------------
// W packed in mma B-fragment order (fp16):
// [L][NCTA][kt=128][np=2][lane=32][8 halfs]; per-CTA slice = 128KB/layer
__device__ __half g_Wp[(size_t)LL * NCTA * 128 * 512];

// Activations packed as A-fragment blocks:
// g_A[p][l][mt=4][kt=128][lane=32][4xu32]; kt 0..63 = X(layer input), 64..127 = H
//   u32 reg order per lane: {a0,a1,a2,a3} = (rlo,klo),(rhi,klo),(rlo,khi),(rhi,khi)
__device__ __half g_A[2][LL][4 * 128 * 256];
__device__ float  g_bias[LL * GG];            // b_ih + b_hh precombined
__device__ unsigned g_bar_cnt;
__device__ unsigned g_bar_gen;

// ---------------------------------------------------------------------------
// Prologue 1: pack W_ih|W_hh (fp32 [L][4H][H] each) into fragment order fp16
// ---------------------------------------------------------------------------
__global__ void pack_weights(const float* __restrict__ Wih,
                             const float* __restrict__ Whh) {
    int tid = blockIdx.x * blockDim.x + threadIdx.x;
    if (tid >= LL * NCTA * 128 * 32) return;
    int lane = tid & 31;
    int kt   = (tid >> 5) & 127;
    int cta  = (tid >> 12) & 127;
    int l    = tid >> 19;
    int c8 = lane >> 2;
    int kq = (lane & 3) * 2;

    #pragma unroll
    for (int np = 0; np < 2; np++) {
        #pragma unroll
        for (int ntl = 0; ntl < 2; ntl++) {
            int nt = np * 2 + ntl;
            int n  = nt * 1024 + cta * 8 + c8;
            __half v[4];
            #pragma unroll
            for (int e = 0; e < 4; e++) {
                int k = kt * 16 + kq + (e & 1) + 8 * (e >> 1);
                float w = (k < HH) ? Wih[((size_t)l * GG + n) * HH + k]
                                   : Whh[((size_t)l * GG + n) * HH + (k - HH)];
                v[e] = __float2half(w);
            }
            size_t off = ((((size_t)(l * NCTA + cta) * 128 + kt) * 2 + np) * 32
                          + lane) * 8 + ntl * 4;
            *(uint2*)&g_Wp[off] = *(uint2*)v;
        }
    }
}

// ---------------------------------------------------------------------------
// Prologue 2: init A (x, h0) into fragment layout; precombine biases
// ---------------------------------------------------------------------------
__global__ void init_state(const float* __restrict__ x,
                           const float* __restrict__ h0,
                           const float* __restrict__ b_ih,
                           const float* __restrict__ b_hh) {
    int i = blockIdx.x * blockDim.x + threadIdx.x;
    if (i < LL * GG) g_bias[i] = b_ih[i] + b_hh[i];
    if (i >= LL * BB * HH) return;
    int k = i & (HH - 1);
    int r = (i >> 10) & (BB - 1);
    int l = i >> 16;

    int mt   = r >> 4;
    int lane = (r & 7) * 4 + ((k & 7) >> 1);
    int reg  = ((r & 15) >> 3) + 2 * ((k & 15) >> 3);
    // halfs offset inside [mt][kt] block of 256 halfs:
    int inblk = lane * 8 + reg * 2 + (k & 1);

    // h0 -> H part (kt = 64 + k/16), parity 0
    g_A[0][l][(mt * 128 + 64 + (k >> 4)) * 256 + inblk] = __float2half(h0[i]);
    // x  -> X part of layer 0, parity 0
    if (l == 0)
        g_A[0][0][(mt * 128 + (k >> 4)) * 256 + inblk] = __float2half(x[r * HH + k]);
}

// ---------------------------------------------------------------------------
// Grid barrier: acq_rel arrive, release flip, acquire poll. 128 CTAs resident.
// ---------------------------------------------------------------------------
__device__ __forceinline__ void grid_sync() {
    __syncthreads();
    if (threadIdx.x == 0) {
        unsigned gen;
        asm volatile("ld.acquire.gpu.global.u32 %0, [%1];"
                     : "=r"(gen) : "l"(&g_bar_gen));
        unsigned prev;
        asm volatile("atom.acq_rel.gpu.global.add.u32 %0, [%1], 1;"
                     : "=r"(prev) : "l"(&g_bar_cnt));
        if (prev == NCTA - 1) {
            asm volatile("st.relaxed.gpu.global.u32 [%0], %1;"
                         :: "l"(&g_bar_cnt), "r"(0u));
            asm volatile("st.release.gpu.global.u32 [%0], %1;"
                         :: "l"(&g_bar_gen), "r"(gen + 1u));
        } else {
            unsigned cur;
            do {
                asm volatile("ld.acquire.gpu.global.u32 %0, [%1];"
                             : "=r"(cur) : "l"(&g_bar_gen));
            } while (cur == gen);
        }
    }
    __syncthreads();
}

__device__ __forceinline__ void mma16816(float* d,
                                         unsigned a0, unsigned a1, unsigned a2, unsigned a3,
                                         unsigned b0, unsigned b1) {
    asm volatile(
        "mma.sync.aligned.m16n8k16.row.col.f32.f16.f16.f32 "
        "{%0,%1,%2,%3},{%4,%5,%6,%7},{%8,%9},{%0,%1,%2,%3};\n"
        : "+f"(d[0]), "+f"(d[1]), "+f"(d[2]), "+f"(d[3])
        : "r"(a0), "r"(a1), "r"(a2), "r"(a3), "r"(b0), "r"(b1));
}

__device__ __forceinline__ float sigm(float v) { return 1.0f / (1.0f + __expf(-v)); }
__device__ __forceinline__ float tanh_fast(float v) {
    return 2.0f / (1.0f + __expf(-2.0f * v)) - 1.0f;
}

// ---------------------------------------------------------------------------
// Persistent LSTM. CTA c owns gate cols {g*1024+j : j in [8c,8c+8)}.
// Warp (ks, wm): m-tile wm, k-tiles [32ks, 32ks+32). ks=1..3 deposit partials
// to SMEM; ks=0 combines and does the register-resident cell update.
// ---------------------------------------------------------------------------
__global__ void __launch_bounds__(NTHR, 1)
lstm_persistent(const float* __restrict__ c0,
                float* __restrict__ out) {
    const int cta  = blockIdx.x;
    const int w    = threadIdx.x >> 5;
    const int lane = threadIdx.x & 31;
    const int ks   = w >> 2;
    const int wm   = w & 3;
    const int qrow = lane >> 2;
    const int tq   = lane & 3;

    __shared__ float s_part[3][4][16][32];   // [ks-1][wm][acc idx][lane]

    // ks==0 threads own cell state for (r = wm*16+qrow(+8), j = cta*8+tq*2(+1))
    float creg[LL][4];
    if (ks == 0) {
        #pragma unroll
        for (int l = 0; l < LL; l++)
            #pragma unroll
            for (int hh2 = 0; hh2 < 2; hh2++)
                #pragma unroll
                for (int u = 0; u < 2; u++) {
                    int r = wm * 16 + qrow + hh2 * 8;
                    int j = cta * 8 + tq * 2 + u;
                    creg[l][hh2 * 2 + u] = c0[((size_t)l * BB + r) * HH + j];
                }
    }

    const char* __restrict__ Wcta =
        (const char*)g_Wp + (size_t)cta * 128 * 1024;   // this CTA's slice, layer 0

    for (int t = 0; t < TT; t++) {
        const int p = t & 1;
        #pragma unroll
        for (int l = 0; l < LL; l++) {
            // A stream: [mt=wm][kt = 32ks .. 32ks+32) blocks of 512B
            const char* Ab = (const char*)g_A[p][l]
                           + (size_t)(wm * 128 + ks * 32) * 512 + lane * 16;
            const char* Wb = Wcta + (size_t)(l * NCTA) * 131072
                           + (size_t)(ks * 32) * 1024 + lane * 16;

            float acc[4][4];
            #pragma unroll
            for (int a = 0; a < 4; a++)
                #pragma unroll
                for (int b = 0; b < 4; b++) acc[a][b] = 0.0f;

            #pragma unroll 4
            for (int kk = 0; kk < 32; kk++) {
                uint4 a   = __ldcg((const uint4*)(Ab + (size_t)kk * 512));
                uint4 w01 = *(const uint4*)(Wb + (size_t)kk * 1024);
                uint4 w23 = *(const uint4*)(Wb + (size_t)kk * 1024 + 512);
                mma16816(acc[0], a.x, a.y, a.z, a.w, w01.x, w01.y);
                mma16816(acc[1], a.x, a.y, a.z, a.w, w01.z, w01.w);
                mma16816(acc[2], a.x, a.y, a.z, a.w, w23.x, w23.y);
                mma16816(acc[3], a.x, a.y, a.z, a.w, w23.z, w23.w);
            }

            if (ks != 0) {
                #pragma unroll
                for (int g = 0; g < 4; g++)
                    #pragma unroll
                    for (int ci = 0; ci < 4; ci++)
                        s_part[ks - 1][wm][g * 4 + ci][lane] = acc[g][ci];
            }
            __syncthreads();

            if (ks == 0) {
                #pragma unroll
                for (int g = 0; g < 4; g++)
                    #pragma unroll
                    for (int ci = 0; ci < 4; ci++)
                        acc[g][ci] += s_part[0][wm][g * 4 + ci][lane]
                                    + s_part[1][wm][g * 4 + ci][lane]
                                    + s_part[2][wm][g * 4 + ci][lane];

                // destinations (fragment-layout u32 stores, own lane)
                char* dstH = (char*)g_A[p ^ 1][l];
                char* dstX = (l < LL - 1) ? (char*)g_A[p][l + 1]
                                          : (char*)g_A[p ^ 1][0];  // y feedback
                int blkH = wm * 128 + 64 + (cta >> 1);
                int blkX = wm * 128 + (cta >> 1);
                int lobytes = lane * 16 + 4 * 2 * (cta & 1);

                const float* __restrict__ bl = g_bias + l * GG;
                int j0 = cta * 8 + tq * 2;

                #pragma unroll
                for (int hh2 = 0; hh2 < 2; hh2++) {
                    int r = wm * 16 + qrow + hh2 * 8;
                    float hn2[2];
                    #pragma unroll
                    for (int u = 0; u < 2; u++) {
                        int j  = j0 + u;
                        int ci = hh2 * 2 + u;
                        float gi = acc[0][ci] + bl[j];
                        float gf = acc[1][ci] + bl[1024 + j];
                        float gg = acc[2][ci] + bl[2048 + j];
                        float go = acc[3][ci] + bl[3072 + j];
                        float ig = sigm(gi), fg = sigm(gf), og = sigm(go);
                        float gt = tanh_fast(gg);
                        float cn = fg * creg[l][ci] + ig * gt;
                        creg[l][ci] = cn;
                        hn2[u] = og * tanh_fast(cn);
                    }
                    unsigned hv = (unsigned)__half_as_ushort(__float2half(hn2[0]))
                                | ((unsigned)__half_as_ushort(__float2half(hn2[1])) << 16);
                    *(unsigned*)(dstH + (size_t)blkH * 512 + lobytes + hh2 * 4) = hv;
                    *(unsigned*)(dstX + (size_t)blkX * 512 + lobytes + hh2 * 4) = hv;
                    if (l == LL - 1)
                        *(float2*)&out[((size_t)r * TT + t) * HH + j0] =
                            make_float2(hn2[0], hn2[1]);
                }
            }
            grid_sync();
        }
    }
}

// ---------------------------------------------------------------------------
// kernel_launch: pack -> init -> persistent run (graph-capturable)
// inputs: x, h0, c0, W_ih, W_hh, b_ih, b_hh, seq_len
// ---------------------------------------------------------------------------
extern "C" void kernel_launch(void* const* d_in, const int* in_sizes, int n_in,
                              void* d_out, int out_size) {
    const float* x   = (const float*)d_in[0];
    const float* h0  = (const float*)d_in[1];
    const float* c0  = (const float*)d_in[2];
    const float* Wih = (const float*)d_in[3];
    const float* Whh = (const float*)d_in[4];
    const float* bih = (const float*)d_in[5];
    const float* bhh = (const float*)d_in[6];
    float* out = (float*)d_out;

    pack_weights<<<(LL * NCTA * 128 * 32) / 256, 256>>>(Wih, Whh);
    init_state<<<(LL * BB * HH + 255) / 256, 256>>>(x, h0, bih, bhh);
    lstm_persistent<<<NCTA, NTHR>>>(c0, out);
}